// round 4
// baseline (speedup 1.0000x reference)
#include <cuda_runtime.h>

#define NV 5
#define NB 2
#define NC 32
#define NH 256
#define NW 320
#define HW (NH*NW)
#define CN 4
#define WPB 8

__device__ float g_proj[NB*(NV-1)*12];
__device__ float g_featT[(size_t)NV*NB*HW*NC];   // [img][p][c]

__global__ void setup_proj_kernel(const float* __restrict__ pm) {
    int t = threadIdx.x;
    if (t >= NB*(NV-1)) return;
    int b  = t / (NV-1);
    int vi = t % (NV-1) + 1;

    double M0[3][3], m0[3], Mi[3][3], mi[3];
    for (int which = 0; which < 2; which++) {
        int v = (which == 0) ? 0 : vi;
        const float* E = pm + ((size_t)(b*NV + v)*2 + 0)*16;
        const float* K = pm + ((size_t)(b*NV + v)*2 + 1)*16;
        double (*M)[3] = (which == 0) ? M0 : Mi;
        double *m      = (which == 0) ? m0 : mi;
        for (int r = 0; r < 3; r++) {
            for (int c = 0; c < 3; c++) {
                double s = 0;
                for (int k = 0; k < 3; k++) s += (double)K[r*4+k] * (double)E[k*4+c];
                M[r][c] = s;
            }
            double s = 0;
            for (int k = 0; k < 3; k++) s += (double)K[r*4+k] * (double)E[k*4+3];
            m[r] = s;
        }
    }
    double a00=M0[0][0],a01=M0[0][1],a02=M0[0][2];
    double a10=M0[1][0],a11=M0[1][1],a12=M0[1][2];
    double a20=M0[2][0],a21=M0[2][1],a22=M0[2][2];
    double det = a00*(a11*a22-a12*a21) - a01*(a10*a22-a12*a20) + a02*(a10*a21-a11*a20);
    double id = 1.0/det;
    double I[3][3];
    I[0][0]=(a11*a22-a12*a21)*id; I[0][1]=(a02*a21-a01*a22)*id; I[0][2]=(a01*a12-a02*a11)*id;
    I[1][0]=(a12*a20-a10*a22)*id; I[1][1]=(a00*a22-a02*a20)*id; I[1][2]=(a02*a10-a00*a12)*id;
    I[2][0]=(a10*a21-a11*a20)*id; I[2][1]=(a01*a20-a00*a21)*id; I[2][2]=(a00*a11-a01*a10)*id;

    double R[3][3], tv[3];
    for (int r = 0; r < 3; r++)
        for (int c = 0; c < 3; c++) {
            double s = 0;
            for (int k = 0; k < 3; k++) s += Mi[r][k]*I[k][c];
            R[r][c] = s;
        }
    for (int r = 0; r < 3; r++) {
        double s = 0;
        for (int k = 0; k < 3; k++) s += R[r][k]*m0[k];
        tv[r] = mi[r] - s;
    }
    float* o = g_proj + t*12;
    o[0]=(float)R[0][0]; o[1]=(float)R[0][1]; o[2]=(float)R[0][2];
    o[3]=(float)R[1][0]; o[4]=(float)R[1][1]; o[5]=(float)R[1][2];
    o[6]=(float)R[2][0]; o[7]=(float)R[2][1]; o[8]=(float)R[2][2];
    o[9]=(float)tv[0]; o[10]=(float)tv[1]; o[11]=(float)tv[2];
}

// CHW -> HWC transpose (proven in R2)
__global__ void __launch_bounds__(256)
transpose_kernel(const float* __restrict__ feat) {
    __shared__ float t[32][33];
    int img = blockIdx.y;
    int hw0 = blockIdx.x * 32;
    const float* src = feat + (size_t)img*NC*HW;
    float* dst = g_featT + (size_t)img*HW*NC;
#pragma unroll
    for (int j = 0; j < 4; j++) {
        int c = threadIdx.y + 8*j;
        t[c][threadIdx.x] = src[(size_t)c*HW + hw0 + threadIdx.x];
    }
    __syncthreads();
#pragma unroll
    for (int j = 0; j < 4; j++) {
        int r = threadIdx.y + 8*j;
        dst[(size_t)(hw0 + r)*NC + threadIdx.x] = t[threadIdx.x][r];
    }
}

// warp = 32 consecutive pixels (one image row segment).
// lane = (d, q): d = lane>>3 (depth), q = lane&7 (channel quad).
__global__ void __launch_bounds__(256, 2)
getcost_kernel(const float* __restrict__ dvals,
               const float* __restrict__ dint,
               const float* __restrict__ vwts,
               float* __restrict__ out)
{
    __shared__ float sproj[NB*(NV-1)*12];
    __shared__ float tileBuf[WPB][32][5];

    for (int i = threadIdx.x; i < NB*(NV-1)*12; i += 256) sproj[i] = g_proj[i];
    __syncthreads();

    int wip  = threadIdx.x >> 5;
    int lane = threadIdx.x & 31;
    int d    = lane >> 3;
    int q    = lane & 7;
    float fd = (float)d;

    int gw   = blockIdx.x * WPB + wip;
    int pix0 = gw * 32;
    int b  = pix0 / HW;
    int p0 = pix0 - b*HW;
    int yy = p0 / NW;
    int xx0 = p0 - yy*NW;
    float fy = (float)yy;

    // view constants (warp-uniform): r-column-0, c = r01*fy + r02, t
    float R0[NV-1], R1[NV-1], R2[NV-1];
    float C0[NV-1], C1[NV-1], C2[NV-1];
    float T0[NV-1], T1[NV-1], T2[NV-1];
#pragma unroll
    for (int j = 0; j < NV-1; j++) {
        const float* PR = sproj + (b*(NV-1) + j)*12;
        R0[j] = PR[0]; R1[j] = PR[3]; R2[j] = PR[6];
        C0[j] = PR[1]*fy + PR[2];
        C1[j] = PR[4]*fy + PR[5];
        C2[j] = PR[7]*fy + PR[8];
        T0[j] = PR[9]; T1[j] = PR[10]; T2[j] = PR[11];
    }

    // per-pixel scalars, lane i <-> pixel i
    float dv_l = __ldg(dvals + pix0 + lane);
    float di_l = __ldg(dint  + pix0 + lane);
    float vw_l[NV-1];
#pragma unroll
    for (int j = 0; j < NV-1; j++)
        vw_l[j] = __ldg(vwts + (size_t)(b*(NV-1)+j)*HW + p0 + lane);

    const float4* refT4 = (const float4*)(g_featT + (size_t)b*HW*NC);
    const unsigned FULL = 0xffffffffu;

#pragma unroll 1
    for (int i = 0; i < 32; i++) {
        int p = p0 + i;
        float fx = (float)(xx0 + i);

        float dvp  = __shfl_sync(FULL, dv_l, i);
        float itv  = __shfl_sync(FULL, di_l, i);
        float invd = __frcp_rn(dvp);
        float low  = invd - (CN*0.5f)*itv;
        float step = itv * ((float)CN/(CN-1));
        float z    = __frcp_rn(low + fd*step);      // this lane's depth

        float sv0 = __shfl_sync(FULL, vw_l[0], i);
        float sv1 = __shfl_sync(FULL, vw_l[1], i);
        float sv2 = __shfl_sync(FULL, vw_l[2], i);
        float sv3 = __shfl_sync(FULL, vw_l[3], i);
        float wsum = 1e-5f + sv0 + sv1 + sv2 + sv3;

        float4 r4 = __ldg(refT4 + p*8 + q);

        float acc = 0.f;
#pragma unroll
        for (int j = 0; j < NV-1; j++) {
            float u0 = fmaf(R0[j], fx, C0[j]);
            float u1 = fmaf(R1[j], fx, C1[j]);
            float u2 = fmaf(R2[j], fx, C2[j]);
            float pz = fmaf(u2, z, T2[j]);
            float rz = __frcp_rn(pz);
            float gx = fmaf(u0, z, T0[j]) * rz;
            float gy = fmaf(u1, z, T1[j]) * rz;

            float x0f = floorf(gx), y0f = floorf(gy);
            float wx = gx - x0f, wy = gy - y0f;

            bool vx0 = (x0f >=  0.f) && (x0f <= (float)(NW-1));
            bool vx1 = (x0f >= -1.f) && (x0f <= (float)(NW-2));
            bool vy0 = (y0f >=  0.f) && (y0f <= (float)(NH-1));
            bool vy1 = (y0f >= -1.f) && (y0f <= (float)(NH-2));

            int x0i = (int)fminf(fmaxf(x0f,       0.f), (float)(NW-1));
            int x1i = (int)fminf(fmaxf(x0f + 1.f, 0.f), (float)(NW-1));
            int y0i = (int)fminf(fmaxf(y0f,       0.f), (float)(NH-1));
            int y1i = (int)fminf(fmaxf(y0f + 1.f, 0.f), (float)(NH-1));

            const float4* vp4 = (const float4*)(g_featT + (size_t)((j+1)*NB + b)*HW*NC);
            int row0 = y0i*NW, row1 = y1i*NW;
            int i00 = (row0 + x0i)*8 + q;
            int i01 = (row0 + x1i)*8 + q;
            int i10 = (row1 + x0i)*8 + q;
            int i11 = (row1 + x1i)*8 + q;

            float4 f00 = __ldg(vp4 + i00);
            float4 f01 = __ldg(vp4 + i01);
            float4 f10 = __ldg(vp4 + i10);
            float4 f11 = __ldg(vp4 + i11);

            float S00 = fmaf(r4.x,f00.x, fmaf(r4.y,f00.y, fmaf(r4.z,f00.z, r4.w*f00.w)));
            float S01 = fmaf(r4.x,f01.x, fmaf(r4.y,f01.y, fmaf(r4.z,f01.z, r4.w*f01.w)));
            float S10 = fmaf(r4.x,f10.x, fmaf(r4.y,f10.y, fmaf(r4.z,f10.z, r4.w*f10.w)));
            float S11 = fmaf(r4.x,f11.x, fmaf(r4.y,f11.y, fmaf(r4.z,f11.z, r4.w*f11.w)));

            float iwx = 1.f - wx, iwy = 1.f - wy;
            float w00 = (vx0 && vy0) ? iwx*iwy : 0.f;
            float w01 = (vx1 && vy0) ? wx*iwy  : 0.f;
            float w10 = (vx0 && vy1) ? iwx*wy  : 0.f;
            float w11 = (vx1 && vy1) ? wx*wy   : 0.f;

            float val = fmaf(w00,S00, fmaf(w01,S01, fmaf(w10,S10, w11*S11)));
            float vwj = (j==0)?sv0:(j==1)?sv1:(j==2)?sv2:sv3;
            acc = fmaf(vwj, val, acc);
        }

        // reduce over the 8 channel-quads within this d-group
        acc += __shfl_xor_sync(FULL, acc, 1);
        acc += __shfl_xor_sync(FULL, acc, 2);
        acc += __shfl_xor_sync(FULL, acc, 4);

        if (q == 0)
            tileBuf[wip][i][d] = acc * __frcp_rn((float)NC * wsum);
    }
    __syncwarp();

    float* ob = out + (size_t)b*NC*CN*HW + p0 + lane;
#pragma unroll
    for (int dd = 0; dd < CN; dd++) {
        float val = tileBuf[wip][lane][dd];
#pragma unroll 8
        for (int c = 0; c < NC; c++)
            ob[(size_t)(c*CN + dd)*HW] = val;
    }
}

extern "C" void kernel_launch(void* const* d_in, const int* in_sizes, int n_in,
                              void* d_out, int out_size) {
    const float *feat = nullptr, *projm = nullptr, *vw = nullptr;
    const float *dv = nullptr, *di = nullptr;
    const int sz_feat = NV*NB*NC*HW;
    const int sz_proj = NB*NV*2*16;
    const int sz_vw   = NB*(NV-1)*HW;
    const int sz_map  = NB*HW;
    for (int i = 0; i < n_in; i++) {
        int s = in_sizes[i];
        if (s == sz_feat)            feat  = (const float*)d_in[i];
        else if (s == sz_proj)       projm = (const float*)d_in[i];
        else if (s == sz_vw)         vw    = (const float*)d_in[i];
        else if (s == sz_map) {
            if (!dv) dv = (const float*)d_in[i];
            else if (!di) di = (const float*)d_in[i];
        }
    }
    float* out = (float*)d_out;

    transpose_kernel<<<dim3(HW/32, NV*NB), dim3(32, 8)>>>(feat);
    setup_proj_kernel<<<1, 32>>>(projm);
    getcost_kernel<<<(NB*HW)/(32*WPB), 256>>>(dv, di, vw, out);
}

// round 5
// speedup vs baseline: 1.8030x; 1.8030x over previous
#include <cuda_runtime.h>
#include <cuda_fp16.h>

#define NV 5
#define NB 2
#define NC 32
#define NH 256
#define NW 320
#define HW (NH*NW)
#define CN 4

__device__ float g_proj[NB*(NV-1)*12];
// fp16-packed source views: [img8 = (v-1)*NB+b][c4][pixel], 4 channels per uint2
__device__ uint2 g_feath[(size_t)(NV-1)*NB*(NC/4)*HW];

__global__ void setup_proj_kernel(const float* __restrict__ pm) {
    int t = threadIdx.x;
    if (t >= NB*(NV-1)) return;
    int b  = t / (NV-1);
    int vi = t % (NV-1) + 1;

    double M0[3][3], m0[3], Mi[3][3], mi[3];
    for (int which = 0; which < 2; which++) {
        int v = (which == 0) ? 0 : vi;
        const float* E = pm + ((size_t)(b*NV + v)*2 + 0)*16;
        const float* K = pm + ((size_t)(b*NV + v)*2 + 1)*16;
        double (*M)[3] = (which == 0) ? M0 : Mi;
        double *m      = (which == 0) ? m0 : mi;
        for (int r = 0; r < 3; r++) {
            for (int c = 0; c < 3; c++) {
                double s = 0;
                for (int k = 0; k < 3; k++) s += (double)K[r*4+k] * (double)E[k*4+c];
                M[r][c] = s;
            }
            double s = 0;
            for (int k = 0; k < 3; k++) s += (double)K[r*4+k] * (double)E[k*4+3];
            m[r] = s;
        }
    }
    double a00=M0[0][0],a01=M0[0][1],a02=M0[0][2];
    double a10=M0[1][0],a11=M0[1][1],a12=M0[1][2];
    double a20=M0[2][0],a21=M0[2][1],a22=M0[2][2];
    double det = a00*(a11*a22-a12*a21) - a01*(a10*a22-a12*a20) + a02*(a10*a21-a11*a20);
    double id = 1.0/det;
    double I[3][3];
    I[0][0]=(a11*a22-a12*a21)*id; I[0][1]=(a02*a21-a01*a22)*id; I[0][2]=(a01*a12-a02*a11)*id;
    I[1][0]=(a12*a20-a10*a22)*id; I[1][1]=(a00*a22-a02*a20)*id; I[1][2]=(a02*a10-a00*a12)*id;
    I[2][0]=(a10*a21-a11*a20)*id; I[2][1]=(a01*a20-a00*a21)*id; I[2][2]=(a00*a11-a01*a10)*id;

    double R[3][3], tv[3];
    for (int r = 0; r < 3; r++)
        for (int c = 0; c < 3; c++) {
            double s = 0;
            for (int k = 0; k < 3; k++) s += Mi[r][k]*I[k][c];
            R[r][c] = s;
        }
    for (int r = 0; r < 3; r++) {
        double s = 0;
        for (int k = 0; k < 3; k++) s += R[r][k]*m0[k];
        tv[r] = mi[r] - s;
    }
    float* o = g_proj + t*12;
    o[0]=(float)R[0][0]; o[1]=(float)R[0][1]; o[2]=(float)R[0][2];
    o[3]=(float)R[1][0]; o[4]=(float)R[1][1]; o[5]=(float)R[1][2];
    o[6]=(float)R[2][0]; o[7]=(float)R[2][1]; o[8]=(float)R[2][2];
    o[9]=(float)tv[0]; o[10]=(float)tv[1]; o[11]=(float)tv[2];
}

// float CHW (views 1..4) -> half4-packed planes
__global__ void __launch_bounds__(256)
convert_kernel(const float* __restrict__ feat) {
    int plane = blockIdx.y;            // 0..63 : img8*8 + c4
    int img8  = plane >> 3;
    int c4    = plane & 7;
    int p = blockIdx.x * 256 + threadIdx.x;
    // source image index = NB + img8 (skip the NB reference images)
    const float* src = feat + ((size_t)(NB + img8)*NC + c4*4)*HW + p;
    float x0 = src[0];
    float x1 = src[HW];
    float x2 = src[2*HW];
    float x3 = src[3*HW];
    __half2 h0 = __floats2half2_rn(x0, x1);
    __half2 h1 = __floats2half2_rn(x2, x3);
    uint2 o;
    o.x = *reinterpret_cast<unsigned*>(&h0);
    o.y = *reinterpret_cast<unsigned*>(&h1);
    g_feath[(size_t)plane*HW + p] = o;
}

__device__ __forceinline__ float2 h2f(unsigned u) {
    __half2 h = *reinterpret_cast<__half2*>(&u);
    return __half22float2(h);
}

__global__ void __launch_bounds__(256)
getcost_kernel(const float* __restrict__ feat,
               const float* __restrict__ dvals,
               const float* __restrict__ dint,
               const float* __restrict__ vwts,
               float* __restrict__ out)
{
    __shared__ float sproj[NB*(NV-1)*12];
    for (int i = threadIdx.x; i < NB*(NV-1)*12; i += 256) sproj[i] = g_proj[i];
    __syncthreads();

    int pix = blockIdx.x * 256 + threadIdx.x;
    int b = pix / HW;
    int p = pix - b*HW;
    int yy = p / NW;
    int xx = p - yy*NW;
    float fx = (float)xx, fy = (float)yy;

    float invd = __frcp_rn(dvals[pix]);
    float itv  = dint[pix];
    float low  = invd - (CN*0.5f)*itv;
    float step = itv * ((float)CN/(CN-1));

    float z[CN];
#pragma unroll
    for (int d = 0; d < CN; d++) z[d] = __frcp_rn(low + (float)d*step);

    float vwr[NV-1];
#pragma unroll
    for (int j = 0; j < NV-1; j++)
        vwr[j] = __ldg(vwts + ((size_t)(b*(NV-1)+j))*HW + p);
    float wsum = 1e-5f + vwr[0] + vwr[1] + vwr[2] + vwr[3];

    // fp32 reference features (coalesced)
    float ref[NC];
    const float* rbase = feat + (size_t)b*NC*HW + p;
#pragma unroll
    for (int c = 0; c < NC; c++) ref[c] = __ldg(rbase + (size_t)c*HW);

    float vol[CN] = {0.f,0.f,0.f,0.f};
    const float* PRb = sproj + b*(NV-1)*12;

#pragma unroll
    for (int vi = 1; vi < NV; vi++) {
        const float* PR = PRb + (vi-1)*12;
        float u0 = fmaf(PR[0], fx, fmaf(PR[1], fy, PR[2]));
        float u1 = fmaf(PR[3], fx, fmaf(PR[4], fy, PR[5]));
        float u2 = fmaf(PR[6], fx, fmaf(PR[7], fy, PR[8]));
        float t0 = PR[9], t1 = PR[10], t2 = PR[11];
        float vw = vwr[vi-1];
        const uint2* fp = g_feath + (size_t)((vi-1)*NB + b)*(NC/4)*HW;

#pragma unroll
        for (int d = 0; d < CN; d++) {
            float zz = z[d];
            float pz = fmaf(u2, zz, t2);
            float rz = __frcp_rn(pz);
            float gx = fmaf(u0, zz, t0) * rz;
            float gy = fmaf(u1, zz, t1) * rz;

            float x0f = floorf(gx), y0f = floorf(gy);
            float wx = gx - x0f, wy = gy - y0f;

            bool vx0 = (x0f >=  0.f) && (x0f <= (float)(NW-1));
            bool vx1 = (x0f >= -1.f) && (x0f <= (float)(NW-2));
            bool vy0 = (y0f >=  0.f) && (y0f <= (float)(NH-1));
            bool vy1 = (y0f >= -1.f) && (y0f <= (float)(NH-2));

            int x0i = (int)fminf(fmaxf(x0f,       0.f), (float)(NW-1));
            int x1i = (int)fminf(fmaxf(x0f + 1.f, 0.f), (float)(NW-1));
            int y0i = (int)fminf(fmaxf(y0f,       0.f), (float)(NH-1));
            int y1i = (int)fminf(fmaxf(y0f + 1.f, 0.f), (float)(NH-1));

            int i00 = y0i*NW + x0i;
            int i01 = y0i*NW + x1i;
            int i10 = y1i*NW + x0i;
            int i11 = y1i*NW + x1i;

            float S00 = 0.f, S01 = 0.f, S10 = 0.f, S11 = 0.f;
#pragma unroll
            for (int c4 = 0; c4 < NC/4; c4++) {
                const uint2* pl = fp + (size_t)c4*HW;
                uint2 a00 = __ldg(pl + i00);
                uint2 a01 = __ldg(pl + i01);
                uint2 a10 = __ldg(pl + i10);
                uint2 a11 = __ldg(pl + i11);
                float r0 = ref[c4*4+0], r1 = ref[c4*4+1];
                float r2 = ref[c4*4+2], r3 = ref[c4*4+3];

                float2 e, o2;
                e = h2f(a00.x); o2 = h2f(a00.y);
                S00 = fmaf(r0,e.x, fmaf(r1,e.y, fmaf(r2,o2.x, fmaf(r3,o2.y, S00))));
                e = h2f(a01.x); o2 = h2f(a01.y);
                S01 = fmaf(r0,e.x, fmaf(r1,e.y, fmaf(r2,o2.x, fmaf(r3,o2.y, S01))));
                e = h2f(a10.x); o2 = h2f(a10.y);
                S10 = fmaf(r0,e.x, fmaf(r1,e.y, fmaf(r2,o2.x, fmaf(r3,o2.y, S10))));
                e = h2f(a11.x); o2 = h2f(a11.y);
                S11 = fmaf(r0,e.x, fmaf(r1,e.y, fmaf(r2,o2.x, fmaf(r3,o2.y, S11))));
            }

            float iwx = 1.f - wx, iwy = 1.f - wy;
            float w00 = (vx0 && vy0) ? iwx*iwy : 0.f;
            float w01 = (vx1 && vy0) ? wx*iwy  : 0.f;
            float w10 = (vx0 && vy1) ? iwx*wy  : 0.f;
            float w11 = (vx1 && vy1) ? wx*wy   : 0.f;

            float val = fmaf(w00,S00, fmaf(w01,S01, fmaf(w10,S10, w11*S11)));
            vol[d] = fmaf(vw, val, vol[d]);
        }
    }

    float scale = __frcp_rn((float)NC * wsum);
#pragma unroll
    for (int d = 0; d < CN; d++) {
        float sim = vol[d] * scale;
        float* ob = out + ((size_t)b*NC*CN + d)*HW + p;
#pragma unroll 8
        for (int c = 0; c < NC; c++) ob[(size_t)c*CN*HW] = sim;
    }
}

extern "C" void kernel_launch(void* const* d_in, const int* in_sizes, int n_in,
                              void* d_out, int out_size) {
    const float *feat = nullptr, *projm = nullptr, *vw = nullptr;
    const float *dv = nullptr, *di = nullptr;
    const int sz_feat = NV*NB*NC*HW;
    const int sz_proj = NB*NV*2*16;
    const int sz_vw   = NB*(NV-1)*HW;
    const int sz_map  = NB*HW;
    for (int i = 0; i < n_in; i++) {
        int s = in_sizes[i];
        if (s == sz_feat)            feat  = (const float*)d_in[i];
        else if (s == sz_proj)       projm = (const float*)d_in[i];
        else if (s == sz_vw)         vw    = (const float*)d_in[i];
        else if (s == sz_map) {
            if (!dv) dv = (const float*)d_in[i];
            else if (!di) di = (const float*)d_in[i];
        }
    }
    float* out = (float*)d_out;

    convert_kernel<<<dim3(HW/256, (NV-1)*NB*(NC/4)), 256>>>(feat);
    setup_proj_kernel<<<1, 32>>>(projm);
    getcost_kernel<<<(NB*HW)/256, 256>>>(feat, dv, di, vw, out);
}